// round 1
// baseline (speedup 1.0000x reference)
#include <cuda_runtime.h>
#include <math.h>

#define NN 100000
#define EE 1200000
#define CC 64
#define HH 64
#define OUTC 10
#define GG 128
#define LL 3
#define EPSBN 1e-5f

// ---------------- scratch (device globals; no allocation allowed) ----------------
__device__ float g_h [NN * HH];   // current node features
__device__ float g_hw[NN * HH];   // post-GEMM features (per conv layer)
__device__ int   g_outdeg[NN];
__device__ int   g_indeg [NN];
__device__ int   g_rowptr[NN + 1];
__device__ int   g_cur   [NN];
__device__ int   g_col   [EE];    // CSR by dst: stores src node id
__device__ float g_dis   [NN];    // deg^-1/2  (deg = outdeg + 1 self loop)
__device__ int   g_bsum  [128];
__device__ int   g_boff  [128];
__device__ float g_ssum  [HH];    // column sum accumulator
__device__ float g_ssq   [HH];    // column sum-of-squares accumulator
__device__ float g_Wp    [HH * HH]; // folded diag(s)*W
__device__ float g_bvec  [HH];      // t @ W
__device__ float g_hg    [GG * HH]; // pooled graph features

// ---------------- setup: degree histogram, dis, CSR ----------------
__global__ void k_zero_deg() {
    int i = blockIdx.x * blockDim.x + threadIdx.x;
    if (i < NN) { g_outdeg[i] = 0; g_indeg[i] = 0; }
}

__global__ void k_hist(const int* __restrict__ src, const int* __restrict__ dst) {
    int e = blockIdx.x * blockDim.x + threadIdx.x;
    if (e < EE) {
        atomicAdd(&g_indeg[dst[e]], 1);
        atomicAdd(&g_outdeg[src[e]], 1);
    }
}

__global__ void k_dis() {
    int i = blockIdx.x * blockDim.x + threadIdx.x;
    if (i < NN) g_dis[i] = rsqrtf((float)g_outdeg[i] + 1.0f);
}

__global__ void k_scan1() {
    __shared__ int sb[1024];
    int t = threadIdx.x;
    int i = blockIdx.x * 1024 + t;
    int v = (i < NN) ? g_indeg[i] : 0;
    sb[t] = v;
    __syncthreads();
    for (int off = 1; off < 1024; off <<= 1) {
        int x = (t >= off) ? sb[t - off] : 0;
        __syncthreads();
        sb[t] += x;
        __syncthreads();
    }
    if (i < NN) g_rowptr[i] = sb[t] - v;          // block-local exclusive
    if (t == 1023) g_bsum[blockIdx.x] = sb[1023]; // block total
}

__global__ void k_scan2(int nb) {
    int run = 0;
    for (int b = 0; b < nb; b++) { g_boff[b] = run; run += g_bsum[b]; }
    g_rowptr[NN] = run;
}

__global__ void k_scan3() {
    int i = blockIdx.x * 1024 + threadIdx.x;
    if (i < NN) {
        int v = g_rowptr[i] + g_boff[blockIdx.x];
        g_rowptr[i] = v;
        g_cur[i] = v;
    }
}

__global__ void k_fill(const int* __restrict__ src, const int* __restrict__ dst) {
    int e = blockIdx.x * blockDim.x + threadIdx.x;
    if (e < EE) {
        int d = dst[e];
        int p = atomicAdd(&g_cur[d], 1);
        g_col[p] = src[e];
    }
}

// ---------------- per-layer: column stats + BN fold ----------------
__global__ void k_zerostat() {
    int t = threadIdx.x;
    if (t < 64) g_ssum[t] = 0.f;
    else        g_ssq[t - 64] = 0.f;
}

__global__ void k_colstats(const float* __restrict__ A, int n) {
    __shared__ float rs[256], rq[256];
    int c  = threadIdx.x & 63;
    int rr = threadIdx.x >> 6;
    int rbeg = blockIdx.x * 512;
    int rend = rbeg + 512; if (rend > n) rend = n;
    float s = 0.f, q = 0.f;
    for (int r = rbeg + rr; r < rend; r += 4) {
        float v = A[(size_t)r * 64 + c];
        s += v; q += v * v;
    }
    rs[threadIdx.x] = s; rq[threadIdx.x] = q;
    __syncthreads();
    if (threadIdx.x < 64) {
        float S = rs[threadIdx.x] + rs[threadIdx.x + 64] + rs[threadIdx.x + 128] + rs[threadIdx.x + 192];
        float Q = rq[threadIdx.x] + rq[threadIdx.x + 64] + rq[threadIdx.x + 128] + rq[threadIdx.x + 192];
        atomicAdd(&g_ssum[threadIdx.x], S);
        atomicAdd(&g_ssq [threadIdx.x], Q);
    }
}

// fold BN (mu/var from accumulators) into W:  Wp = diag(s)W, bvec = t @ W
__global__ void k_fold(const float* __restrict__ gam, const float* __restrict__ bet,
                       const float* __restrict__ W, int n) {
    __shared__ float s_s[64], s_t[64];
    int c = threadIdx.x;
    float invn = 1.0f / (float)n;
    float mu  = g_ssum[c] * invn;
    float var = g_ssq[c] * invn - mu * mu;
    var = fmaxf(var, 0.f);
    float inv = rsqrtf(var + EPSBN);
    float sc = inv * gam[c];
    s_s[c] = sc;
    s_t[c] = bet[c] - mu * sc;
    __syncthreads();
    float bv = 0.f;
    #pragma unroll 8
    for (int k = 0; k < 64; k++) {
        float w = W[k * 64 + c];
        g_Wp[k * 64 + c] = s_s[k] * w;
        bv += s_t[k] * w;
    }
    g_bvec[c] = bv;
}

// ---------------- GEMM: out[n,64] = A[n,64] @ g_Wp (+bvec +bias2, optional relu) ----------------
__global__ __launch_bounds__(256)
void k_gemm(const float* __restrict__ A, const float* __restrict__ bias2,
            float* __restrict__ out, int n, int relu, int useBvec) {
    __shared__ float sA[64 * 128];   // sA[k*128 + r] (k-major, transposed)
    __shared__ float sW[64 * 64];
    int tid = threadIdx.x;
    int rowBase = blockIdx.x * 128;

    for (int i = tid * 4; i < 4096; i += 1024)
        *(float4*)(sW + i) = *(const float4*)(g_Wp + i);

    int lane = tid & 31, wid = tid >> 5;
    int k0 = wid * 8;
    #pragma unroll
    for (int rp = 0; rp < 4; rp++) {
        int r = rp * 32 + lane;
        int grow = rowBase + r;
        float4 v0 = make_float4(0.f, 0.f, 0.f, 0.f), v1 = v0;
        if (grow < n) {
            const float4* p = (const float4*)(A + (size_t)grow * 64 + k0);
            v0 = p[0]; v1 = p[1];
        }
        sA[(k0 + 0) * 128 + r] = v0.x;
        sA[(k0 + 1) * 128 + r] = v0.y;
        sA[(k0 + 2) * 128 + r] = v0.z;
        sA[(k0 + 3) * 128 + r] = v0.w;
        sA[(k0 + 4) * 128 + r] = v1.x;
        sA[(k0 + 5) * 128 + r] = v1.y;
        sA[(k0 + 6) * 128 + r] = v1.z;
        sA[(k0 + 7) * 128 + r] = v1.w;
    }
    __syncthreads();

    int cx = (tid & 15) * 4;   // output col base
    int ry = (tid >> 4) * 8;   // output row base
    float acc[8][4];
    #pragma unroll
    for (int i = 0; i < 8; i++)
        #pragma unroll
        for (int j = 0; j < 4; j++) acc[i][j] = 0.f;

    #pragma unroll
    for (int k = 0; k < 64; k++) {
        float4 w  = *(const float4*)(sW + k * 64 + cx);
        float4 a0 = *(const float4*)(sA + k * 128 + ry);
        float4 a1 = *(const float4*)(sA + k * 128 + ry + 4);
        float a[8] = {a0.x, a0.y, a0.z, a0.w, a1.x, a1.y, a1.z, a1.w};
        #pragma unroll
        for (int i = 0; i < 8; i++) {
            acc[i][0] = fmaf(a[i], w.x, acc[i][0]);
            acc[i][1] = fmaf(a[i], w.y, acc[i][1]);
            acc[i][2] = fmaf(a[i], w.z, acc[i][2]);
            acc[i][3] = fmaf(a[i], w.w, acc[i][3]);
        }
    }

    float b[4] = {0.f, 0.f, 0.f, 0.f};
    if (useBvec) {
        #pragma unroll
        for (int j = 0; j < 4; j++) b[j] = g_bvec[cx + j];
    }
    if (bias2) {
        #pragma unroll
        for (int j = 0; j < 4; j++) b[j] += bias2[cx + j];
    }
    #pragma unroll
    for (int i = 0; i < 8; i++) {
        int grow = rowBase + ry + i;
        if (grow < n) {
            float4 o;
            o.x = acc[i][0] + b[0];
            o.y = acc[i][1] + b[1];
            o.z = acc[i][2] + b[2];
            o.w = acc[i][3] + b[3];
            if (relu) {
                o.x = fmaxf(o.x, 0.f); o.y = fmaxf(o.y, 0.f);
                o.z = fmaxf(o.z, 0.f); o.w = fmaxf(o.w, 0.f);
            }
            *(float4*)(out + (size_t)grow * 64 + cx) = o;
        }
    }
}

// ---------------- aggregation (pull, warp per node): h = relu(agg + wsum*bvec + b) ----------------
__global__ __launch_bounds__(256)
void k_agg(const float* __restrict__ bconv) {
    int gtid = blockIdx.x * 256 + threadIdx.x;
    int i = gtid >> 5;
    int lane = gtid & 31;
    if (i >= NN) return;
    int c0 = lane * 2;
    float di = g_dis[i];
    int e = g_rowptr[i], end = g_rowptr[i + 1];
    float a0 = 0.f, a1 = 0.f, ws = 0.f;
    for (; e < end; e++) {
        int s = g_col[e];
        float w = di * g_dis[s];
        float2 v = *(const float2*)&g_hw[(size_t)s * 64 + c0];
        a0 = fmaf(w, v.x, a0);
        a1 = fmaf(w, v.y, a1);
        ws += w;
    }
    // self loop
    {
        float w = di * di;
        float2 v = *(const float2*)&g_hw[(size_t)i * 64 + c0];
        a0 = fmaf(w, v.x, a0);
        a1 = fmaf(w, v.y, a1);
        ws += w;
    }
    float o0 = a0 + ws * g_bvec[c0]     + bconv[c0];
    float o1 = a1 + ws * g_bvec[c0 + 1] + bconv[c0 + 1];
    float2 o = make_float2(fmaxf(o0, 0.f), fmaxf(o1, 0.f));
    *(float2*)&g_h[(size_t)i * 64 + c0] = o;
}

// ---------------- pooling (sorted batch_idx; warp per 16 nodes, flush on boundary) ----------------
__global__ void k_zerohg() {
    int i = blockIdx.x * blockDim.x + threadIdx.x;
    if (i < GG * HH) g_hg[i] = 0.f;
}

__global__ void k_pool(const int* __restrict__ batch) {
    int gtid = blockIdx.x * 256 + threadIdx.x;
    int warp = gtid >> 5;
    int lane = gtid & 31;
    int n0 = warp * 16;
    if (n0 >= NN) return;
    int nend = n0 + 16; if (nend > NN) nend = NN;
    int c0 = lane * 2;
    float a0 = 0.f, a1 = 0.f;
    int curg = batch[n0];
    for (int nd = n0; nd < nend; nd++) {
        int g = batch[nd];
        if (g != curg) {
            atomicAdd(&g_hg[curg * 64 + c0],     a0);
            atomicAdd(&g_hg[curg * 64 + c0 + 1], a1);
            a0 = 0.f; a1 = 0.f; curg = g;
        }
        float2 v = *(const float2*)&g_h[(size_t)nd * 64 + c0];
        a0 += v.x; a1 += v.y;
    }
    atomicAdd(&g_hg[curg * 64 + c0],     a0);
    atomicAdd(&g_hg[curg * 64 + c0 + 1], a1);
}

// ---------------- final head: BN -> FC -> ReLU -> BN -> cls -> log_softmax ----------------
__global__ __launch_bounds__(256, 1)
void k_final(const float* __restrict__ bn1g, const float* __restrict__ bn1b,
             const float* __restrict__ Wfc,  const float* __restrict__ bfc,
             const float* __restrict__ bn2g, const float* __restrict__ bn2b,
             const float* __restrict__ Wcls, const float* __restrict__ bcls,
             float* __restrict__ out) {
    __shared__ float sA[128 * 65];
    __shared__ float red[256], red2[256];
    __shared__ float s_s[64], s_t[64];
    int tid = threadIdx.x;
    int c = tid & 63, rr = tid >> 6;

    for (int i = tid; i < 128 * 64; i += 256)
        sA[(i >> 6) * 65 + (i & 63)] = g_hg[i];
    __syncthreads();

    // stats 1
    float s = 0.f, q = 0.f;
    for (int r = rr; r < 128; r += 4) {
        float v = sA[r * 65 + c];
        s += v; q += v * v;
    }
    red[tid] = s; red2[tid] = q;
    __syncthreads();
    if (tid < 64) {
        float S = red [tid] + red [tid + 64] + red [tid + 128] + red [tid + 192];
        float Q = red2[tid] + red2[tid + 64] + red2[tid + 128] + red2[tid + 192];
        float mu = S * (1.f / 128.f);
        float var = fmaxf(Q * (1.f / 128.f) - mu * mu, 0.f);
        float inv = rsqrtf(var + EPSBN);
        float sc = inv * bn1g[tid];
        s_s[tid] = sc;
        s_t[tid] = bn1b[tid] - mu * sc;
    }
    __syncthreads();
    // BN1 in place
    for (int r = rr; r < 128; r += 4)
        sA[r * 65 + c] = sA[r * 65 + c] * s_s[c] + s_t[c];
    __syncthreads();

    // FC GEMM: thread owns col c, rows rr, rr+4, ...
    float wreg[64];
    #pragma unroll
    for (int k = 0; k < 64; k++) wreg[k] = Wfc[k * 64 + c];
    float acc[32];
    for (int ri = 0; ri < 32; ri++) {
        int r = rr + ri * 4;
        float a = bfc[c];
        #pragma unroll
        for (int k = 0; k < 64; k++) a = fmaf(sA[r * 65 + k], wreg[k], a);
        acc[ri] = fmaxf(a, 0.f);
    }
    __syncthreads();
    for (int ri = 0; ri < 32; ri++) sA[(rr + ri * 4) * 65 + c] = acc[ri];
    __syncthreads();

    // stats 2
    s = 0.f; q = 0.f;
    for (int r = rr; r < 128; r += 4) {
        float v = sA[r * 65 + c];
        s += v; q += v * v;
    }
    red[tid] = s; red2[tid] = q;
    __syncthreads();
    if (tid < 64) {
        float S = red [tid] + red [tid + 64] + red [tid + 128] + red [tid + 192];
        float Q = red2[tid] + red2[tid + 64] + red2[tid + 128] + red2[tid + 192];
        float mu = S * (1.f / 128.f);
        float var = fmaxf(Q * (1.f / 128.f) - mu * mu, 0.f);
        float inv = rsqrtf(var + EPSBN);
        float sc = inv * bn2g[tid];
        s_s[tid] = sc;
        s_t[tid] = bn2b[tid] - mu * sc;
    }
    __syncthreads();

    // cls GEMM + log_softmax: thread per row
    if (tid < 128) {
        int r = tid;
        float logits[10];
        #pragma unroll
        for (int j = 0; j < 10; j++) logits[j] = bcls[j];
        for (int k = 0; k < 64; k++) {
            float v = sA[r * 65 + k] * s_s[k] + s_t[k];
            #pragma unroll
            for (int j = 0; j < 10; j++)
                logits[j] = fmaf(v, Wcls[k * 10 + j], logits[j]);
        }
        float m = logits[0];
        #pragma unroll
        for (int j = 1; j < 10; j++) m = fmaxf(m, logits[j]);
        float se = 0.f;
        #pragma unroll
        for (int j = 0; j < 10; j++) se += expf(logits[j] - m);
        float lse = logf(se) + m;
        #pragma unroll
        for (int j = 0; j < 10; j++) out[r * 10 + j] = logits[j] - lse;
    }
}

// ---------------- host launch ----------------
extern "C" void kernel_launch(void* const* d_in, const int* in_sizes, int n_in,
                              void* d_out, int out_size) {
    const float* x         = (const float*)d_in[0];
    const int*   ei        = (const int*)  d_in[1];
    const int*   batch     = (const int*)  d_in[2];
    const float* bn_feat_g = (const float*)d_in[3];
    const float* bn_feat_b = (const float*)d_in[4];
    const float* W_feat    = (const float*)d_in[5];
    const float* b_feat    = (const float*)d_in[6];
    const float* conv_bn_g = (const float*)d_in[7];
    const float* conv_bn_b = (const float*)d_in[8];
    const float* conv_W    = (const float*)d_in[9];
    const float* conv_b    = (const float*)d_in[10];
    const float* bn_fc_g   = (const float*)d_in[11];
    const float* bn_fc_b   = (const float*)d_in[12];
    const float* W_fc      = (const float*)d_in[13];
    const float* b_fc      = (const float*)d_in[14];
    const float* bn_hid_g  = (const float*)d_in[15];
    const float* bn_hid_b  = (const float*)d_in[16];
    const float* W_cls     = (const float*)d_in[17];
    const float* b_cls     = (const float*)d_in[18];
    float* out = (float*)d_out;

    void *ph_v, *phw_v;
    cudaGetSymbolAddress(&ph_v,  g_h);
    cudaGetSymbolAddress(&phw_v, g_hw);
    float* ph  = (float*)ph_v;
    float* phw = (float*)phw_v;

    const int* src = ei;
    const int* dst = ei + EE;

    const int nbScan = (NN + 1023) / 1024;       // 98
    const int nbNode = (NN + 255) / 256;         // 391
    const int nbEdge = (EE + 255) / 256;         // 4688
    const int nbStat = (NN + 511) / 512;         // 196
    const int nbGemm = (NN + 127) / 128;         // 782
    const int nbAgg  = (NN * 32 + 255) / 256;    // 12500
    const int nbPool = (((NN + 15) / 16) * 32 + 255) / 256;

    // ---- CSR build ----
    k_zero_deg<<<nbNode, 256>>>();
    k_hist<<<nbEdge, 256>>>(src, dst);
    k_dis<<<nbNode, 256>>>();
    k_scan1<<<nbScan, 1024>>>();
    k_scan2<<<1, 1>>>(nbScan);
    k_scan3<<<nbScan, 1024>>>();
    k_fill<<<nbEdge, 256>>>(src, dst);

    // ---- feat layer: h = relu(BN(x) @ W_feat + b_feat) ----
    k_zerostat<<<1, 128>>>();
    k_colstats<<<nbStat, 256>>>(x, NN);
    k_fold<<<1, 64>>>(bn_feat_g, bn_feat_b, W_feat, NN);
    k_gemm<<<nbGemm, 256>>>(x, b_feat, ph, NN, 1, 1);

    // ---- conv layers ----
    for (int l = 0; l < LL; l++) {
        k_zerostat<<<1, 128>>>();
        k_colstats<<<nbStat, 256>>>(ph, NN);
        k_fold<<<1, 64>>>(conv_bn_g + l * HH, conv_bn_b + l * HH, conv_W + l * HH * HH, NN);
        k_gemm<<<nbGemm, 256>>>(ph, (const float*)0, phw, NN, 0, 0);
        k_agg<<<nbAgg, 256>>>(conv_b + l * HH);
    }

    // ---- pool + head ----
    k_zerohg<<<32, 256>>>();
    k_pool<<<nbPool, 256>>>(batch);
    k_final<<<1, 256>>>(bn_fc_g, bn_fc_b, W_fc, b_fc,
                        bn_hid_g, bn_hid_b, W_cls, b_cls, out);
}